// round 5
// baseline (speedup 1.0000x reference)
#include <cuda_runtime.h>
#include <math.h>

// ---------------------------------------------------------------------------
// SuperPointMatching_OT — single persistent kernel with software grid barriers.
// inner[i,j] = exp(ms[i,j]) * ref[i] * src[j]   (i,j in [0,8192); ms stride 8193)
// thres = first t in {0.5, 0.5-0.01f, ...} with count(inner > t) >= 2048
// outputs (24576 fp32): ref_idx[8192] | src_idx[8192] | scores[8192]
// ---------------------------------------------------------------------------

#define STRIDE   8193u
#define NELEM    (8193u * 8193u)     // 67,125,249; tail element = dustbin corner
#define NVEC     (NELEM / 4u)        // 16,781,312 float4s
#define TOTAL    (8192u * 8192u)
#define KCORR    2048u
#define MAXCORR  8192
#define NTHRES   64
#define K_SPEC   45                  // speculative cutoff bucket (T[45] ~ 0.05)
#define LOGCUT   (-3.0f)             // exp(-3)<T[45], ref*src<1 => safe reject
#define CAP      (2u * 1024u * 1024u)
#define FCAP     65536u
#define PCAP     (1024u * 1024u)     // global overflow list for shared-list spill
#define SVECCAP  10240u              // per-block shared hit list (expected ~5K)
#define NB       296u                // 2 blocks/SM x 148 SMs -> all co-resident
#define NTH      256u

__device__ unsigned dHist[NTHRES];
__device__ float    dThres;
__device__ unsigned dDeep;           // 0=no, 1=partial deep hist, 2=full deep hist
__device__ unsigned dRecollect;
__device__ unsigned dCollected, dNF, dNPre;
__device__ unsigned dPre[PCAP];
__device__ unsigned dCandIdx[CAP];
__device__ float    dCandVal[CAP];
__device__ unsigned dFIdx[FCAP];
__device__ float    dFVal[FCAP];
__device__ unsigned gCount, gRelease;   // monotonic grid-barrier state

// ---------------------------------------------------------------------------
__device__ __forceinline__ void grid_bar() {
    __syncthreads();
    if (threadIdx.x == 0) {
        __threadfence();
        unsigned arrival = atomicAdd(&gCount, 1u) + 1u;
        unsigned target = ((arrival + NB - 1u) / NB) * NB;
        if (arrival == target) atomicMax(&gRelease, target);
        else while (atomicAdd(&gRelease, 0u) < target) __nanosleep(64);
        __threadfence();
    }
    __syncthreads();
}

__device__ __forceinline__ void build_table(float* T) {
    float t = 0.5f;
#pragma unroll
    for (int k = 0; k < NTHRES; k++) { T[k] = t; t = t - 0.01f; }
}

// Smallest k in [0, kmax] with v > T[k].
__device__ __forceinline__ int find_bucket(float v, const float* T, int kmax) {
    int k = (int)((0.5f - v) * 100.0f) - 2;
    k = k < 0 ? 0 : (k > kmax ? kmax : k);
    while (k > 0 && v > T[k - 1]) k--;
    while (k < kmax && !(v > T[k])) k++;
    return k;
}

// Warp-aggregated append. MUST be called convergent (uniform trip counts).
__device__ __forceinline__ unsigned agg_append(unsigned* ctr, bool want) {
    unsigned lane = threadIdx.x & 31u;
    unsigned mask = __ballot_sync(0xFFFFFFFFu, want);
    unsigned pos = 0xFFFFFFFFu;
    if (want) {
        unsigned rank = __popc(mask & ((1u << lane) - 1u));
        int leader = __ffs((int)mask) - 1;
        unsigned base = 0;
        if ((int)lane == leader) base = atomicAdd(ctr, __popc(mask));
        base = __shfl_sync(mask, base, leader);
        pos = base + rank;
    }
    return pos;
}

// Same, but counter lives in shared memory.
__device__ __forceinline__ unsigned agg_append_sh(unsigned* ctr, bool want) {
    unsigned lane = threadIdx.x & 31u;
    unsigned mask = __ballot_sync(0xFFFFFFFFu, want);
    unsigned pos = 0xFFFFFFFFu;
    if (want) {
        unsigned rank = __popc(mask & ((1u << lane) - 1u));
        int leader = __ffs((int)mask) - 1;
        unsigned base = 0;
        if ((int)lane == leader) base = atomicAdd(ctr, __popc(mask));
        base = __shfl_sync(mask, base, leader);
        pos = base + rank;
    }
    return pos;
}

// ---------------------------------------------------------------------------
__global__ void __launch_bounds__(NTH, 2)
k_mega(const float4* __restrict__ ms4, const float* __restrict__ ms,
       const float* __restrict__ refw, const float* __restrict__ srcw,
       float* __restrict__ out, int out_size)
{
    __shared__ float    T[NTHRES];
    __shared__ unsigned sHist[NTHRES];
    __shared__ unsigned sN;
    __shared__ unsigned sVec[SVECCAP];      // reused as u16 hist / rank buffer

    const unsigned tid  = threadIdx.x;
    const unsigned gid  = blockIdx.x * NTH + tid;
    const unsigned step = NB * NTH;

    if (tid == 0) { build_table(T); sN = 0u; }
    if (tid < NTHRES) sHist[tid] = 0u;
    __syncthreads();
    const float tspec = T[K_SPEC];

    // ---- S0: default-fill output ------------------------------------------
    for (unsigned j = gid; j < (unsigned)out_size; j += step)
        out[j] = (j < 2u * MAXCORR) ? -1.0f : 0.0f;

    // ---- S1a: pure stream, push hit float4-indices to shared list ---------
    {
        const unsigned niter = (NVEC + step - 1u) / step;   // uniform
        for (unsigned k = 0; k < niter; k += 4u) {
            float4 a[4]; unsigned vp[4]; bool ok[4];
#pragma unroll
            for (int u = 0; u < 4; u++) {
                unsigned kk = k + (unsigned)u;
                vp[u] = gid + kk * step;
                ok[u] = (kk < niter) && (vp[u] < NVEC);
                a[u] = ok[u] ? __ldcs(ms4 + vp[u])
                             : make_float4(-1e30f, -1e30f, -1e30f, -1e30f);
            }
#pragma unroll
            for (int u = 0; u < 4; u++) {
                float mx = fmaxf(fmaxf(a[u].x, a[u].y), fmaxf(a[u].z, a[u].w));
                bool hit = ok[u] && (mx > LOGCUT);
                unsigned pos = agg_append_sh(&sN, hit);
                if (hit) {
                    if (pos < SVECCAP) sVec[pos] = vp[u];
                    else {
                        unsigned g = atomicAdd(&dNPre, 1u);
                        if (g < PCAP) dPre[g] = vp[u];
                    }
                }
            }
        }
    }
    __syncthreads();

    // ---- S1b: block-local dense processing of the hit list -----------------
    {
        unsigned n = sN < SVECCAP ? sN : SVECCAP;
        unsigned dn = (n + NTH - 1u) / NTH;                 // block-uniform
        for (unsigned q0 = 0; q0 < dn; q0++) {
            unsigned p = q0 * NTH + tid;
            bool pok = p < n;
            unsigned vp = pok ? sVec[p] : 0u;
            float4 a = pok ? __ldg(ms4 + vp)
                           : make_float4(-1e30f, -1e30f, -1e30f, -1e30f);
            float mv[4] = {a.x, a.y, a.z, a.w};
#pragma unroll
            for (int c = 0; c < 4; c++) {
                float m = mv[c];
                bool want = false; float v = 0.0f; unsigned id = 0u;
                if (pok && m > LOGCUT) {
                    unsigned pe = vp * 4u + (unsigned)c;
                    unsigned i = pe / STRIDE;
                    unsigned j = pe - i * STRIDE;
                    if (i < 8192u && j < 8192u) {
                        v = __fmul_rn(expf(m), __fmul_rn(refw[i], srcw[j]));
                        if (v > tspec) {
                            want = true; id = (i << 13) | j;
                            atomicAdd(&sHist[find_bucket(v, T, K_SPEC)], 1u);
                        }
                    }
                }
                unsigned g = agg_append(&dCollected, want);
                if (want && g < CAP) { dCandIdx[g] = id; dCandVal[g] = v; }
            }
        }
    }
    __syncthreads();
    if (tid < NTHRES && sHist[tid]) atomicAdd(&dHist[tid], sHist[tid]);

    grid_bar();                                             // BAR 1

    // ---- S1c: process global overflow list (normally empty) ----------------
    {
        unsigned novf = atomicAdd(&dNPre, 0u);
        if (novf > 0u) {
            unsigned n = novf < PCAP ? novf : PCAP;
            unsigned niter = (n + step - 1u) / step;
            for (unsigned k = 0; k < niter; k++) {
                unsigned q = gid + k * step;
                bool qok = q < n;
                unsigned vp = qok ? dPre[q] : 0u;
                float4 a = qok ? __ldg(ms4 + vp)
                               : make_float4(-1e30f, -1e30f, -1e30f, -1e30f);
                float mv[4] = {a.x, a.y, a.z, a.w};
#pragma unroll
                for (int c = 0; c < 4; c++) {
                    float m = mv[c];
                    bool want = false; float v = 0.0f; unsigned id = 0u;
                    if (qok && m > LOGCUT) {
                        unsigned pe = vp * 4u + (unsigned)c;
                        unsigned i = pe / STRIDE;
                        unsigned j = pe - i * STRIDE;
                        if (i < 8192u && j < 8192u) {
                            v = __fmul_rn(expf(m), __fmul_rn(refw[i], srcw[j]));
                            if (v > tspec) {
                                want = true; id = (i << 13) | j;
                                atomicAdd(&dHist[find_bucket(v, T, K_SPEC)], 1u);
                            }
                        }
                    }
                    unsigned g = agg_append(&dCollected, want);
                    if (want && g < CAP) { dCandIdx[g] = id; dCandVal[g] = v; }
                }
            }
            grid_bar();                                     // BAR 1b (uniform)
        }
    }

    // ---- S2: threshold from histogram (block 0) ----------------------------
    if (blockIdx.x == 0) {
        if (tid < NTHRES) sHist[tid] = dHist[tid];
        __syncthreads();
        if (tid == 0) {
            if (atomicAdd(&dNPre, 0u) > PCAP) {             // spill lost: full redo
                for (int k = 0; k < NTHRES; k++) dHist[k] = 0u;
                dDeep = 2u; dRecollect = 1u; dCollected = 0u;
            } else {
                unsigned cum = 0; int ks = -1;
                for (int k = 0; k <= K_SPEC; k++) {
                    cum += sHist[k];
                    if (cum >= KCORR) { ks = k; break; }
                }
                if (ks < 0) { dDeep = 1u; dRecollect = 1u; dCollected = 0u; }
                else {
                    dThres = T[ks];
                    if (dCollected > CAP) { dRecollect = 1u; dCollected = 0u; }
                }
            }
        }
        __syncthreads();
    }
    grid_bar();                                             // BAR 2

    // ---- S3: fallback deep histogram + recollect (normally skipped) --------
    {
        unsigned deep = atomicAdd(&dDeep, 0u);
        if (deep) {
            unsigned short (*h)[32] =
                (unsigned short (*)[32])sVec;               // [8*NTHRES][32] u16
            for (unsigned p = tid; p < 8u * NTHRES * 32u / 2u; p += NTH)
                ((unsigned*)h)[p] = 0u;
            __syncthreads();
            bool full = (deep == 2u);
            unsigned wrp = tid >> 5, lane = tid & 31u;
            for (unsigned idx = gid; idx < TOTAL; idx += step) {
                unsigned i = idx >> 13, j = idx & 8191u;
                float m = __ldg(ms + i * STRIDE + j);
                float v = __fmul_rn(expf(m), __fmul_rn(refw[i], srcw[j]));
                if (full || !(v > tspec)) {
                    int k = find_bucket(v, T, NTHRES - 1);
                    h[wrp * NTHRES + k][lane]++;
                }
            }
            __syncthreads();
            if (tid < NTHRES) {
                unsigned s = 0;
                for (int wq = 0; wq < 8; wq++)
                    for (int l = 0; l < 32; l++) s += h[wq * NTHRES + tid][l];
                if (s) atomicAdd(&dHist[tid], s);
            }
            grid_bar();                                     // BAR 3a
            if (blockIdx.x == 0) {
                if (tid < NTHRES) sHist[tid] = dHist[tid];
                __syncthreads();
                if (tid == 0) {
                    unsigned cum = 0; int ks = NTHRES - 1;
                    for (int k = 0; k < NTHRES; k++) {
                        cum += sHist[k];
                        if (cum >= KCORR) { ks = k; break; }
                    }
                    dThres = T[ks];
                }
                __syncthreads();
            }
            grid_bar();                                     // BAR 3b
        }
        unsigned rec = atomicAdd(&dRecollect, 0u);
        if (rec) {
            float th = dThres;
            float lcut = (th > 1e-30f) ? (logf(th) - 0.02f) : -1e30f;
            const unsigned niter = (TOTAL + step - 1u) / step;
            for (unsigned k = 0; k < niter; k++) {
                unsigned idx = gid + k * step;
                bool ok = idx < TOTAL;
                bool want = false; float v = 0.0f;
                if (ok) {
                    unsigned i = idx >> 13, j = idx & 8191u;
                    float m = __ldg(ms + i * STRIDE + j);
                    if (m > lcut) {
                        v = __fmul_rn(expf(m), __fmul_rn(refw[i], srcw[j]));
                        want = (v > th);
                    }
                }
                unsigned g = agg_append(&dCollected, want);
                if (want && g < CAP) { dCandIdx[g] = idx; dCandVal[g] = v; }
            }
            grid_bar();                                     // BAR 3c
        }
    }

    // ---- S4: compact candidates above final threshold ----------------------
    {
        unsigned n = atomicAdd(&dCollected, 0u); if (n > CAP) n = CAP;
        float th = dThres;
        const unsigned niter = (n + step - 1u) / step;
        for (unsigned k = 0; k < niter; k++) {
            unsigned q = gid + k * step;
            bool ok = q < n;
            float v = ok ? dCandVal[q] : 0.0f;
            bool want = ok && (v > th);
            unsigned g = agg_append(&dNF, want);
            if (want && g < FCAP) { dFIdx[g] = dCandIdx[q]; dFVal[g] = v; }
        }
    }
    grid_bar();                                             // BAR 4

    // ---- S5: rank (row-major position) + write output ----------------------
    {
        unsigned nF = atomicAdd(&dNF, 0u); if (nF > FCAP) nF = FCAP;
        if (blockIdx.x * NTH < nF) {                        // block-uniform skip
            unsigned Li = (gid < nF) ? dFIdx[gid] : 0xFFFFFFFFu;
            float    Vi = (gid < nF) ? dFVal[gid] : 0.0f;
            unsigned rank = 0;
            for (unsigned base = 0; base < nF; base += 4096u) {
                unsigned m = nF - base; if (m > 4096u) m = 4096u;
                __syncthreads();
                for (unsigned p = tid; p < m; p += NTH) sVec[p] = dFIdx[base + p];
                __syncthreads();
                if (gid < nF)
                    for (unsigned p = 0; p < m; p++) rank += (sVec[p] < Li) ? 1u : 0u;
            }
            if (gid < nF && rank < (unsigned)MAXCORR) {
                unsigned r = Li >> 13, c = Li & 8191u;
                out[rank]               = (float)r;
                out[MAXCORR + rank]     = (float)c;
                out[2 * MAXCORR + rank] = Vi;
            }
        }
    }
    grid_bar();                                             // BAR 5

    // ---- S6: reset state for next graph replay -----------------------------
    if (blockIdx.x == 0 && tid == 0) {
        for (int k = 0; k < NTHRES; k++) dHist[k] = 0u;
        dCollected = 0u; dNF = 0u; dNPre = 0u;
        dDeep = 0u; dRecollect = 0u; dThres = 0.0f;
        __threadfence();
    }
}

// ---------------------------------------------------------------------------
extern "C" void kernel_launch(void* const* d_in, const int* in_sizes, int n_in,
                              void* d_out, int out_size) {
    const float* ms   = (const float*)d_in[0];   // (8193, 8193) f32
    const float* refw = (const float*)d_in[1];   // (8192,) f32
    const float* srcw = (const float*)d_in[2];   // (8192,) f32
    float* out = (float*)d_out;                  // 24576 f32

    k_mega<<<NB, NTH>>>((const float4*)ms, ms, refw, srcw, out, out_size);
}

// round 6
// speedup vs baseline: 1.1830x; 1.1830x over previous
#include <cuda_runtime.h>
#include <math.h>

// ---------------------------------------------------------------------------
// SuperPointMatching_OT — 2 kernels:
//   A: max-occupancy pure stream -> hit bitmap (1 bit per float4)
//   B: persistent grid (barriers) -> process hits, threshold, rank, output
// inner[i,j] = exp(ms[i,j]) * ref[i] * src[j]   (i,j in [0,8192); stride 8193)
// thres = first t in {0.5, 0.5-0.01f, ...} with count(inner > t) >= 2048
// outputs (24576 fp32): ref_idx[8192] | src_idx[8192] | scores[8192]
// ---------------------------------------------------------------------------

#define STRIDE   8193u
#define NELEM    (8193u * 8193u)       // 67,125,249; last elem = dustbin corner
#define NVEC     (NELEM / 4u)          // 16,781,312 float4s (exact /32)
#define NWORDS   (NVEC / 32u)          // 524,416 bitmap words (exact)
#define TOTAL    (8192u * 8192u)
#define KCORR    2048u
#define MAXCORR  8192
#define NTHRES   64
#define K_SPEC   45                    // speculative cutoff bucket (T[45]~0.05)
#define LOGCUT   (-3.0f)               // exp(-3)<T[45], ref*src<1 => safe reject
#define CAP      (1024u * 1024u)
#define FCAP     65536u
#define NB_A     8194u                 // 8194*2048 float4s == NVEC exactly
#define NB_B     296u                  // 2/SM x 148 SMs co-resident
#define NTH      256u
#define STEP_B   (NB_B * NTH)

__device__ unsigned dBitmap[NWORDS];
__device__ unsigned dHist[NTHRES];
__device__ float    dThres;
__device__ unsigned dDeep;             // 0 none, 1 partial deep hist, 2 full
__device__ unsigned dRecollect;
__device__ unsigned dCollected, dNF;
__device__ unsigned dCandIdx[CAP];
__device__ float    dCandVal[CAP];
__device__ unsigned dFIdx[FCAP];
__device__ float    dFVal[FCAP];
__device__ unsigned gCount, gRelease;  // monotonic grid barrier

// ---------------------------------------------------------------------------
__device__ __forceinline__ void grid_bar() {
    __syncthreads();
    if (threadIdx.x == 0) {
        __threadfence();
        unsigned arrival = atomicAdd(&gCount, 1u) + 1u;
        unsigned target = ((arrival + NB_B - 1u) / NB_B) * NB_B;
        if (arrival == target) atomicMax(&gRelease, target);
        else while (atomicAdd(&gRelease, 0u) < target) __nanosleep(64);
        __threadfence();
    }
    __syncthreads();
}

__device__ __forceinline__ void build_table(float* T) {
    float t = 0.5f;
#pragma unroll
    for (int k = 0; k < NTHRES; k++) { T[k] = t; t = t - 0.01f; }
}

// Smallest k in [0, kmax] with v > T[k].
__device__ __forceinline__ int find_bucket(float v, const float* T, int kmax) {
    int k = (int)((0.5f - v) * 100.0f) - 2;
    k = k < 0 ? 0 : (k > kmax ? kmax : k);
    while (k > 0 && v > T[k - 1]) k--;
    while (k < kmax && !(v > T[k])) k++;
    return k;
}

// ---------------------------------------------------------------------------
// Kernel A: pure stream. 1 bit per float4 (max component > LOGCUT).
// Block b covers float4s [b*2048, b*2048+2048); thread (w,l) does k*256+w*32+l.
// Ballot word (k, w) covers a contiguous 32-float4 range -> word b*64 + k*8 + w.
__global__ void __launch_bounds__(NTH) k_stream(const float4* __restrict__ ms4,
                                                float* __restrict__ out,
                                                int out_size) {
    const unsigned tid = threadIdx.x;
    const unsigned w = tid >> 5, l = tid & 31u;
    const unsigned base = blockIdx.x * 2048u;

    // default-fill output (first blocks only do real work here)
    unsigned gid = blockIdx.x * NTH + tid;
    if (gid < (unsigned)out_size)
        out[gid] = (gid < 2u * MAXCORR) ? -1.0f : 0.0f;

    float4 a[8];
#pragma unroll
    for (int k = 0; k < 8; k++)
        a[k] = __ldcs(ms4 + base + (unsigned)k * 256u + w * 32u + l);

    unsigned word = 0u;
#pragma unroll
    for (int k = 0; k < 8; k++) {
        float mx = fmaxf(fmaxf(a[k].x, a[k].y), fmaxf(a[k].z, a[k].w));
        unsigned msk = __ballot_sync(0xFFFFFFFFu, mx > LOGCUT);
        if (l == (unsigned)k) word = msk;
    }
    if (l < 8u) dBitmap[blockIdx.x * 64u + l * 8u + w] = word;
}

// ---------------------------------------------------------------------------
// Kernel B: persistent; bitmap -> hist+candidates -> threshold -> (fallbacks)
// -> compact -> rank -> output -> reset.  NO ballots in divergent regions.
__global__ void __launch_bounds__(NTH, 2)
k_post(const float4* __restrict__ ms4, const float* __restrict__ ms,
       const float* __restrict__ refw, const float* __restrict__ srcw,
       float* __restrict__ out)
{
    __shared__ float    T[NTHRES];
    __shared__ unsigned sHist[NTHRES];
    __shared__ unsigned sBuf[8192];        // 32KB: deep-hist u16 / rank staging

    const unsigned tid = threadIdx.x;
    const unsigned gid = blockIdx.x * NTH + tid;

    if (tid == 0) build_table(T);
    if (tid < NTHRES) sHist[tid] = 0u;
    __syncthreads();
    const float tspec = T[K_SPEC];

    // ---- S1: process bitmap hits ------------------------------------------
    for (unsigned wi = gid; wi < NWORDS; wi += STEP_B) {
        unsigned word = dBitmap[wi];
        while (word) {
            int b = __ffs(word) - 1; word &= word - 1u;
            unsigned vp = wi * 32u + (unsigned)b;
            float4 a = __ldg(ms4 + vp);
            float mv[4] = {a.x, a.y, a.z, a.w};
#pragma unroll
            for (int c = 0; c < 4; c++) {
                float m = mv[c];
                if (m > LOGCUT) {
                    unsigned pe = vp * 4u + (unsigned)c;
                    unsigned i = pe / STRIDE;
                    unsigned j = pe - i * STRIDE;
                    if (i < 8192u && j < 8192u) {
                        float v = __fmul_rn(expf(m),
                                            __fmul_rn(__ldg(refw + i), __ldg(srcw + j)));
                        if (v > tspec) {
                            atomicAdd(&sHist[find_bucket(v, T, K_SPEC)], 1u);
                            unsigned g = atomicAdd(&dCollected, 1u);
                            if (g < CAP) { dCandIdx[g] = (i << 13) | j; dCandVal[g] = v; }
                        }
                    }
                }
            }
        }
    }
    __syncthreads();
    if (tid < NTHRES && sHist[tid]) atomicAdd(&dHist[tid], sHist[tid]);
    grid_bar();                                             // BAR 1

    // ---- S2: threshold (block 0, hist staged through 64 threads) ----------
    if (blockIdx.x == 0) {
        if (tid < NTHRES) sHist[tid] = dHist[tid];
        __syncthreads();
        if (tid == 0) {
            unsigned cum = 0; int ks = -1;
            for (int k = 0; k <= K_SPEC; k++) {
                cum += sHist[k];
                if (cum >= KCORR) { ks = k; break; }
            }
            if (ks < 0) { dDeep = 1u; dRecollect = 1u; dCollected = 0u; }
            else {
                dThres = T[ks];
                if (dCollected > CAP) { dRecollect = 1u; dCollected = 0u; }
            }
        }
        __syncthreads();
    }
    grid_bar();                                             // BAR 2

    // ---- S3: fallbacks (normally skipped; grid-uniform flags) -------------
    {
        unsigned deep = atomicAdd(&dDeep, 0u);
        if (deep) {
            unsigned short (*h)[32] = (unsigned short (*)[32])sBuf; // [8*64][32]
            for (unsigned p = tid; p < 8u * NTHRES * 32u / 2u; p += NTH)
                sBuf[p] = 0u;
            __syncthreads();
            bool full = (deep == 2u);
            unsigned wrp = tid >> 5, lane = tid & 31u;
            for (unsigned idx = gid; idx < TOTAL; idx += STEP_B) {
                unsigned i = idx >> 13, j = idx & 8191u;
                float m = __ldg(ms + i * STRIDE + j);
                float v = __fmul_rn(expf(m), __fmul_rn(refw[i], srcw[j]));
                if (full || !(v > tspec)) {
                    int k = find_bucket(v, T, NTHRES - 1);
                    h[wrp * NTHRES + k][lane]++;
                }
            }
            __syncthreads();
            if (tid < NTHRES) {
                unsigned s = 0;
                for (int wq = 0; wq < 8; wq++)
                    for (int lq = 0; lq < 32; lq++) s += h[wq * NTHRES + tid][lq];
                if (s) atomicAdd(&dHist[tid], s);
            }
            grid_bar();                                     // BAR 3a
            if (blockIdx.x == 0 && tid == 0) {
                unsigned cum = 0; int ks = NTHRES - 1;
                for (int k = 0; k < NTHRES; k++) {
                    cum += dHist[k];
                    if (cum >= KCORR) { ks = k; break; }
                }
                dThres = T[ks];
            }
            grid_bar();                                     // BAR 3b
        }
        unsigned rec = atomicAdd(&dRecollect, 0u);
        if (rec) {
            float th = dThres;
            float lcut = (th > 1e-30f) ? (logf(th) - 0.02f) : -1e30f;
            for (unsigned idx = gid; idx < TOTAL; idx += STEP_B) {
                unsigned i = idx >> 13, j = idx & 8191u;
                float m = __ldg(ms + i * STRIDE + j);
                if (m > lcut) {
                    float v = __fmul_rn(expf(m), __fmul_rn(refw[i], srcw[j]));
                    if (v > th) {
                        unsigned g = atomicAdd(&dCollected, 1u);
                        if (g < CAP) { dCandIdx[g] = (i << 13) | j; dCandVal[g] = v; }
                    }
                }
            }
            grid_bar();                                     // BAR 3c
        }
    }

    // ---- S4: compact candidates above final threshold ----------------------
    {
        unsigned n = atomicAdd(&dCollected, 0u); if (n > CAP) n = CAP;
        float th = dThres;
        for (unsigned q = gid; q < n; q += STEP_B) {
            float v = dCandVal[q];
            if (v > th) {
                unsigned g = atomicAdd(&dNF, 1u);
                if (g < FCAP) { dFIdx[g] = dCandIdx[q]; dFVal[g] = v; }
            }
        }
    }
    grid_bar();                                             // BAR 4

    // ---- S5: rank (row-major position) + write output ----------------------
    {
        unsigned nF = atomicAdd(&dNF, 0u); if (nF > FCAP) nF = FCAP;
        if (blockIdx.x * NTH < nF) {                        // block-uniform skip
            unsigned Li = (gid < nF) ? dFIdx[gid] : 0xFFFFFFFFu;
            float    Vi = (gid < nF) ? dFVal[gid] : 0.0f;
            unsigned rank = 0;
            for (unsigned base = 0; base < nF; base += 8192u) {
                unsigned m = nF - base; if (m > 8192u) m = 8192u;
                __syncthreads();
                for (unsigned p = tid; p < m; p += NTH) sBuf[p] = dFIdx[base + p];
                __syncthreads();
                if (gid < nF)
                    for (unsigned p = 0; p < m; p++) rank += (sBuf[p] < Li) ? 1u : 0u;
            }
            if (gid < nF && rank < (unsigned)MAXCORR) {
                unsigned r = Li >> 13, c = Li & 8191u;
                out[rank]               = (float)r;
                out[MAXCORR + rank]     = (float)c;
                out[2 * MAXCORR + rank] = Vi;
            }
        }
    }
    grid_bar();                                             // BAR 5

    // ---- S6: reset state for next graph replay -----------------------------
    if (blockIdx.x == 0 && tid == 0) {
        for (int k = 0; k < NTHRES; k++) dHist[k] = 0u;
        dCollected = 0u; dNF = 0u;
        dDeep = 0u; dRecollect = 0u; dThres = 0.0f;
        __threadfence();
    }
}

// ---------------------------------------------------------------------------
extern "C" void kernel_launch(void* const* d_in, const int* in_sizes, int n_in,
                              void* d_out, int out_size) {
    const float* ms   = (const float*)d_in[0];   // (8193, 8193) f32
    const float* refw = (const float*)d_in[1];   // (8192,) f32
    const float* srcw = (const float*)d_in[2];   // (8192,) f32
    float* out = (float*)d_out;                  // 24576 f32

    k_stream<<<NB_A, NTH>>>((const float4*)ms, out, out_size);
    k_post<<<NB_B, NTH>>>((const float4*)ms, ms, refw, srcw, out);
}

// round 7
// speedup vs baseline: 3.5334x; 2.9867x over previous
#include <cuda_runtime.h>
#include <math.h>

// ---------------------------------------------------------------------------
// SuperPointMatching_OT — pipeline:
//   k_reset    : zero counters (tiny)
//   k_stream   : full-occupancy pure stream -> hit bitmap (1 bit / float4)
//   k_process  : bitmap hits -> histogram + candidates (shared staging)
//   k_thres    : threshold from histogram (parallel hist load)
//   k_fb_hist / k_thres2 / k_collect2 : gated fallbacks (normally ~no-op)
//   k_compact  : candidates > final threshold
//   k_rank     : row-major rank -> ordered output
// inner[i,j] = exp(ms[i,j]) * ref[i] * src[j]; stride 8193
// thres = first t in {0.5, 0.5-0.01f, ...} with count(inner > t) >= 2048
// out (24576 f32): ref_idx[8192] | src_idx[8192] | scores[8192]
// ---------------------------------------------------------------------------

#define STRIDE   8193u
#define NELEM    (8193u * 8193u)       // 67,125,249; last elem = dustbin corner
#define NVEC     (NELEM / 4u)          // 16,781,312 float4s (exact /32)
#define NWORDS   (NVEC / 32u)          // 524,416 bitmap words
#define TOTAL    (8192u * 8192u)
#define KCORR    2048u
#define MAXCORR  8192
#define NTHRES   64
#define K_SPEC   45                    // speculative cutoff bucket (T[45]~0.05)
#define LOGCUT   (-3.0f)               // exp(-3)<T[45], ref*src<1 => safe reject
#define CAP      (1024u * 1024u)
#define FCAP     65536u
#define SCAND    2048u                 // per-block candidate staging
#define BUFCAP   3072u
#define NB_A     8194u                 // 8194*2048 float4s == NVEC exactly
#define NTH      256u

__device__ unsigned dBitmap[NWORDS];
__device__ unsigned dHist[NTHRES];
__device__ float    dThres;
__device__ unsigned dDeep, dRecollect;
__device__ unsigned dCollected, dNF;
__device__ unsigned dCandIdx[CAP];
__device__ float    dCandVal[CAP];
__device__ unsigned dFIdx[FCAP];
__device__ float    dFVal[FCAP];

__device__ __forceinline__ void build_table(float* T) {
    float t = 0.5f;
#pragma unroll
    for (int k = 0; k < NTHRES; k++) { T[k] = t; t = t - 0.01f; }
}

// Smallest k in [0, kmax] with v > T[k].
__device__ __forceinline__ int find_bucket(float v, const float* T, int kmax) {
    int k = (int)((0.5f - v) * 100.0f) - 2;
    k = k < 0 ? 0 : (k > kmax ? kmax : k);
    while (k > 0 && v > T[k - 1]) k--;
    while (k < kmax && !(v > T[k])) k++;
    return k;
}

// ---------------------------------------------------------------------------
__global__ void k_reset() {
    unsigned i = threadIdx.x;
    if (i < NTHRES) dHist[i] = 0u;
    if (i == 64u) { dCollected = 0u; dNF = 0u; }
    if (i == 65u) { dDeep = 0u; dRecollect = 0u; dThres = 0.0f; }
}

// ---------------------------------------------------------------------------
// Pure stream: 1 bit per float4 (max component > LOGCUT). Also fills output.
// Block b covers float4s [b*2048, (b+1)*2048); ballot word (k,w) is contiguous.
__global__ void __launch_bounds__(NTH) k_stream(const float4* __restrict__ ms4,
                                                float* __restrict__ out,
                                                int out_size) {
    const unsigned tid = threadIdx.x;
    const unsigned w = tid >> 5, l = tid & 31u;
    const unsigned base = blockIdx.x * 2048u;

    unsigned gid = blockIdx.x * NTH + tid;
    if (gid < (unsigned)out_size)
        out[gid] = (gid < 2u * MAXCORR) ? -1.0f : 0.0f;

    float4 a[8];
#pragma unroll
    for (int k = 0; k < 8; k++)
        a[k] = __ldcs(ms4 + base + (unsigned)k * 256u + w * 32u + l);

    unsigned word = 0u;
#pragma unroll
    for (int k = 0; k < 8; k++) {
        float mx = fmaxf(fmaxf(a[k].x, a[k].y), fmaxf(a[k].z, a[k].w));
        unsigned msk = __ballot_sync(0xFFFFFFFFu, mx > LOGCUT);
        if (l == (unsigned)k) word = msk;
    }
    if (l < 8u) dBitmap[blockIdx.x * 64u + l * 8u + w] = word;
}

// ---------------------------------------------------------------------------
// Bitmap hits -> histogram (<=K_SPEC) + candidates. Shared staging; the only
// global same-address atomic is ONE reservation per block (plus rare spill).
__global__ void __launch_bounds__(NTH) k_process(const float4* __restrict__ ms4,
                                                 const float* __restrict__ refw,
                                                 const float* __restrict__ srcw) {
    __shared__ float    T[NTHRES];
    __shared__ unsigned sHist[NTHRES];
    __shared__ unsigned sN, sBase;
    __shared__ unsigned sIdx[SCAND];
    __shared__ float    sVal[SCAND];

    const unsigned tid = threadIdx.x;
    if (tid == 0) { build_table(T); sN = 0u; }
    if (tid < NTHRES) sHist[tid] = 0u;
    __syncthreads();
    const float tspec = T[K_SPEC];

    const unsigned step = gridDim.x * NTH;
    for (unsigned wi = blockIdx.x * NTH + tid; wi < NWORDS; wi += step) {
        unsigned word = dBitmap[wi];
        while (word) {
            int b = __ffs(word) - 1; word &= word - 1u;
            unsigned vp = wi * 32u + (unsigned)b;
            float4 a = __ldg(ms4 + vp);
            float mv[4] = {a.x, a.y, a.z, a.w};
#pragma unroll
            for (int c = 0; c < 4; c++) {
                float m = mv[c];
                if (m > LOGCUT) {
                    unsigned pe = vp * 4u + (unsigned)c;
                    unsigned i = pe / STRIDE;
                    unsigned j = pe - i * STRIDE;
                    if (i < 8192u && j < 8192u) {
                        float v = __fmul_rn(expf(m),
                                            __fmul_rn(refw[i], srcw[j]));
                        if (v > tspec) {
                            atomicAdd(&sHist[find_bucket(v, T, K_SPEC)], 1u);
                            unsigned p = atomicAdd(&sN, 1u);
                            if (p < SCAND) {
                                sIdx[p] = (i << 13) | j; sVal[p] = v;
                            } else {            // rare spill
                                unsigned g = atomicAdd(&dCollected, 1u);
                                if (g < CAP) {
                                    dCandIdx[g] = (i << 13) | j; dCandVal[g] = v;
                                }
                            }
                        }
                    }
                }
            }
        }
    }
    __syncthreads();
    if (tid < NTHRES && sHist[tid]) atomicAdd(&dHist[tid], sHist[tid]);
    if (tid == 0) {
        unsigned n = sN < SCAND ? sN : SCAND;
        sBase = atomicAdd(&dCollected, n);
    }
    __syncthreads();
    unsigned n = sN < SCAND ? sN : SCAND;
    for (unsigned p = tid; p < n; p += NTH) {
        unsigned g = sBase + p;
        if (g < CAP) { dCandIdx[g] = sIdx[p]; dCandVal[g] = sVal[p]; }
    }
}

// ---------------------------------------------------------------------------
__global__ void k_thres() {
    __shared__ unsigned sH[NTHRES];
    unsigned tid = threadIdx.x;
    if (tid < NTHRES) sH[tid] = dHist[tid];     // one coalesced load
    __syncthreads();
    if (tid == 0) {
        float T[NTHRES];
        build_table(T);
        unsigned cum = 0; int ks = -1;
        for (int k = 0; k <= K_SPEC; k++) {
            cum += sH[k];
            if (cum >= KCORR) { ks = k; break; }
        }
        if (ks < 0) { dDeep = 1u; dRecollect = 1u; dCollected = 0u; }
        else {
            dThres = T[ks];
            if (dCollected > CAP) { dRecollect = 1u; dCollected = 0u; }
        }
    }
}

// ---------------------------------------------------------------------------
// Fallback full-depth histogram (no-op unless dDeep).
__global__ void __launch_bounds__(NTH) k_fb_hist(const float* __restrict__ ms,
                                                 const float* __restrict__ refw,
                                                 const float* __restrict__ srcw) {
    if (dDeep == 0u) return;
    __shared__ unsigned short h[8][NTHRES][32];
    __shared__ float T[NTHRES];
    const unsigned tid = threadIdx.x;
    if (tid == 0) build_table(T);
    {
        unsigned* hz = (unsigned*)h;
        for (unsigned p = tid; p < 8u * NTHRES * 32u / 2u; p += NTH) hz[p] = 0u;
    }
    __syncthreads();
    const float tspec = T[K_SPEC];
    const unsigned wrp = tid >> 5, lane = tid & 31u;
    const unsigned step = gridDim.x * NTH;
    for (unsigned idx = blockIdx.x * NTH + tid; idx < TOTAL; idx += step) {
        unsigned i = idx >> 13, j = idx & 8191u;
        float m = __ldg(ms + i * STRIDE + j);
        float v = __fmul_rn(expf(m), __fmul_rn(refw[i], srcw[j]));
        if (!(v > tspec)) {
            int k = find_bucket(v, T, NTHRES - 1);
            h[wrp][k][lane]++;
        }
    }
    __syncthreads();
    if (tid < NTHRES) {
        unsigned s = 0;
        for (int wq = 0; wq < 8; wq++)
            for (int lq = 0; lq < 32; lq++) s += h[wq][tid][lq];
        if (s) atomicAdd(&dHist[tid], s);
    }
}

__global__ void k_thres2() {
    if (dDeep == 0u) return;
    __shared__ unsigned sH[NTHRES];
    unsigned tid = threadIdx.x;
    if (tid < NTHRES) sH[tid] = dHist[tid];
    __syncthreads();
    if (tid == 0) {
        float T[NTHRES];
        build_table(T);
        unsigned cum = 0; int ks = NTHRES - 1;
        for (int k = 0; k < NTHRES; k++) {
            cum += sH[k];
            if (cum >= KCORR) { ks = k; break; }
        }
        dThres = T[ks];
    }
}

// ---------------------------------------------------------------------------
// Re-collection with the final threshold (no-op unless dRecollect).
__global__ void __launch_bounds__(NTH) k_collect2(const float* __restrict__ ms,
                                                  const float* __restrict__ refw,
                                                  const float* __restrict__ srcw) {
    if (dRecollect == 0u) return;
    __shared__ unsigned sN, sBase;
    __shared__ unsigned sIdx[BUFCAP];
    __shared__ float    sVal[BUFCAP];
    const unsigned tid = threadIdx.x;
    if (tid == 0) sN = 0u;
    __syncthreads();
    const float th = dThres;
    float lcut = (th > 1e-30f) ? (logf(th) - 0.02f) : -1e30f;
    const unsigned step = gridDim.x * NTH;
    for (unsigned idx = blockIdx.x * NTH + tid; idx < TOTAL; idx += step) {
        unsigned i = idx >> 13, j = idx & 8191u;
        float m = __ldg(ms + i * STRIDE + j);
        if (m > lcut) {
            float v = __fmul_rn(expf(m), __fmul_rn(refw[i], srcw[j]));
            if (v > th) {
                unsigned p = atomicAdd(&sN, 1u);
                if (p < BUFCAP) { sIdx[p] = (i << 13) | j; sVal[p] = v; }
                else {
                    unsigned g = atomicAdd(&dCollected, 1u);
                    if (g < CAP) { dCandIdx[g] = (i << 13) | j; dCandVal[g] = v; }
                }
            }
        }
    }
    __syncthreads();
    if (tid == 0) {
        unsigned n = sN < BUFCAP ? sN : BUFCAP;
        sBase = atomicAdd(&dCollected, n);
    }
    __syncthreads();
    unsigned n = sN < BUFCAP ? sN : BUFCAP;
    for (unsigned p = tid; p < n; p += NTH) {
        unsigned g = sBase + p;
        if (g < CAP) { dCandIdx[g] = sIdx[p]; dCandVal[g] = sVal[p]; }
    }
}

// ---------------------------------------------------------------------------
__global__ void k_compact() {
    unsigned n = dCollected < CAP ? dCollected : CAP;
    unsigned step = gridDim.x * blockDim.x;
    float th = dThres;
    for (unsigned q = blockIdx.x * blockDim.x + threadIdx.x; q < n; q += step) {
        float v = dCandVal[q];
        if (v > th) {
            unsigned g = atomicAdd(&dNF, 1u);
            if (g < FCAP) { dFIdx[g] = dCandIdx[q]; dFVal[g] = v; }
        }
    }
}

// ---------------------------------------------------------------------------
// Rank-based ordered write: slot = #{passing candidates with smaller index}.
__global__ void k_rank(float* out) {
    __shared__ unsigned sBuf[4096];
    unsigned n = dNF < FCAP ? dNF : FCAP;
    if (blockIdx.x * blockDim.x >= n) return;   // uniform per block

    unsigned i = blockIdx.x * blockDim.x + threadIdx.x;
    unsigned Li = (i < n) ? dFIdx[i] : 0xFFFFFFFFu;
    float    Vi = (i < n) ? dFVal[i] : 0.0f;
    unsigned rank = 0;
    for (unsigned base = 0; base < n; base += 4096u) {
        unsigned m = n - base; if (m > 4096u) m = 4096u;
        __syncthreads();
        for (unsigned p = threadIdx.x; p < m; p += blockDim.x) sBuf[p] = dFIdx[base + p];
        __syncthreads();
        if (i < n)
            for (unsigned p = 0; p < m; p++) rank += (sBuf[p] < Li) ? 1u : 0u;
    }
    if (i < n && rank < (unsigned)MAXCORR) {
        unsigned r = Li >> 13, c = Li & 8191u;
        out[rank]               = (float)r;
        out[MAXCORR + rank]     = (float)c;
        out[2 * MAXCORR + rank] = Vi;
    }
}

// ---------------------------------------------------------------------------
extern "C" void kernel_launch(void* const* d_in, const int* in_sizes, int n_in,
                              void* d_out, int out_size) {
    const float* ms   = (const float*)d_in[0];   // (8193, 8193) f32
    const float* refw = (const float*)d_in[1];   // (8192,) f32
    const float* srcw = (const float*)d_in[2];   // (8192,) f32
    float* out = (float*)d_out;                  // 24576 f32

    k_reset<<<1, 128>>>();
    k_stream<<<NB_A, NTH>>>((const float4*)ms, out, out_size);
    k_process<<<2048, NTH>>>((const float4*)ms, refw, srcw);
    k_thres<<<1, 64>>>();
    k_fb_hist<<<512, NTH>>>(ms, refw, srcw);     // no-op unless dDeep
    k_thres2<<<1, 64>>>();                       // no-op unless dDeep
    k_collect2<<<512, NTH>>>(ms, refw, srcw);    // no-op unless dRecollect
    k_compact<<<64, NTH>>>();
    k_rank<<<256, NTH>>>(out);
}

// round 8
// speedup vs baseline: 3.5434x; 1.0028x over previous
#include <cuda_runtime.h>
#include <math.h>

// ---------------------------------------------------------------------------
// SuperPointMatching_OT — pipeline:
//   k_reset    : zero counters (tiny)
//   k_stream   : full-occupancy pure stream -> hit bitmap (1 bit / float4)
//   k_process  : bitmap hits -> histogram + candidates (shared staging)
//   k_thres    : threshold from histogram (parallel hist load)
//   k_fb_hist / k_thres2 / k_collect2 : gated fallbacks (normally ~no-op)
//   k_compact  : candidates > final threshold
//   k_rank     : row-major rank -> ordered output
// inner[i,j] = exp(ms[i,j]) * ref[i] * src[j]; stride 8193
// thres = first t in {0.5, 0.5-0.01f, ...} with count(inner > t) >= 2048
// out (24576 f32): ref_idx[8192] | src_idx[8192] | scores[8192]
// ---------------------------------------------------------------------------

#define STRIDE   8193u
#define NELEM    (8193u * 8193u)       // 67,125,249; last elem = dustbin corner
#define NVEC     (NELEM / 4u)          // 16,781,312 float4s (exact /32)
#define NWORDS   (NVEC / 32u)          // 524,416 bitmap words
#define TOTAL    (8192u * 8192u)
#define KCORR    2048u
#define MAXCORR  8192
#define NTHRES   64
#define K_SPEC   45                    // speculative cutoff bucket (T[45]~0.05)
#define LOGCUT   (-3.0f)               // exp(-3)<T[45], ref*src<1 => safe reject
#define CAP      (1024u * 1024u)
#define FCAP     65536u
#define SCAND    2048u                 // per-block candidate staging
#define BUFCAP   3072u
#define NB_A     8194u                 // 8194*2048 float4s == NVEC exactly
#define NTH      256u

__device__ unsigned dBitmap[NWORDS];
__device__ unsigned dHist[NTHRES];
__device__ float    dThres;
__device__ unsigned dDeep, dRecollect;
__device__ unsigned dCollected, dNF;
__device__ unsigned dCandIdx[CAP];
__device__ float    dCandVal[CAP];
__device__ unsigned dFIdx[FCAP];
__device__ float    dFVal[FCAP];

__device__ __forceinline__ void build_table(float* T) {
    float t = 0.5f;
#pragma unroll
    for (int k = 0; k < NTHRES; k++) { T[k] = t; t = t - 0.01f; }
}

// Smallest k in [0, kmax] with v > T[k].
__device__ __forceinline__ int find_bucket(float v, const float* T, int kmax) {
    int k = (int)((0.5f - v) * 100.0f) - 2;
    k = k < 0 ? 0 : (k > kmax ? kmax : k);
    while (k > 0 && v > T[k - 1]) k--;
    while (k < kmax && !(v > T[k])) k++;
    return k;
}

// ---------------------------------------------------------------------------
__global__ void k_reset() {
    unsigned i = threadIdx.x;
    if (i < NTHRES) dHist[i] = 0u;
    if (i == 64u) { dCollected = 0u; dNF = 0u; }
    if (i == 65u) { dDeep = 0u; dRecollect = 0u; dThres = 0.0f; }
}

// ---------------------------------------------------------------------------
// Pure stream: 1 bit per float4 (max component > LOGCUT). Also fills output.
// Block b covers float4s [b*2048, (b+1)*2048); ballot word (k,w) is contiguous.
__global__ void __launch_bounds__(NTH) k_stream(const float4* __restrict__ ms4,
                                                float* __restrict__ out,
                                                int out_size) {
    const unsigned tid = threadIdx.x;
    const unsigned w = tid >> 5, l = tid & 31u;
    const unsigned base = blockIdx.x * 2048u;

    unsigned gid = blockIdx.x * NTH + tid;
    if (gid < (unsigned)out_size)
        out[gid] = (gid < 2u * MAXCORR) ? -1.0f : 0.0f;

    float4 a[8];
#pragma unroll
    for (int k = 0; k < 8; k++)
        a[k] = __ldcs(ms4 + base + (unsigned)k * 256u + w * 32u + l);

    unsigned word = 0u;
#pragma unroll
    for (int k = 0; k < 8; k++) {
        float mx = fmaxf(fmaxf(a[k].x, a[k].y), fmaxf(a[k].z, a[k].w));
        unsigned msk = __ballot_sync(0xFFFFFFFFu, mx > LOGCUT);
        if (l == (unsigned)k) word = msk;
    }
    if (l < 8u) dBitmap[blockIdx.x * 64u + l * 8u + w] = word;
}

// ---------------------------------------------------------------------------
// Bitmap hits -> histogram (<=K_SPEC) + candidates. Shared staging; the only
// global same-address atomic is ONE reservation per block (plus rare spill).
__global__ void __launch_bounds__(NTH) k_process(const float4* __restrict__ ms4,
                                                 const float* __restrict__ refw,
                                                 const float* __restrict__ srcw) {
    __shared__ float    T[NTHRES];
    __shared__ unsigned sHist[NTHRES];
    __shared__ unsigned sN, sBase;
    __shared__ unsigned sIdx[SCAND];
    __shared__ float    sVal[SCAND];

    const unsigned tid = threadIdx.x;
    if (tid == 0) { build_table(T); sN = 0u; }
    if (tid < NTHRES) sHist[tid] = 0u;
    __syncthreads();
    const float tspec = T[K_SPEC];

    const unsigned step = gridDim.x * NTH;
    for (unsigned wi = blockIdx.x * NTH + tid; wi < NWORDS; wi += step) {
        unsigned word = dBitmap[wi];
        while (word) {
            int b = __ffs(word) - 1; word &= word - 1u;
            unsigned vp = wi * 32u + (unsigned)b;
            float4 a = __ldg(ms4 + vp);
            float mv[4] = {a.x, a.y, a.z, a.w};
#pragma unroll
            for (int c = 0; c < 4; c++) {
                float m = mv[c];
                if (m > LOGCUT) {
                    unsigned pe = vp * 4u + (unsigned)c;
                    unsigned i = pe / STRIDE;
                    unsigned j = pe - i * STRIDE;
                    if (i < 8192u && j < 8192u) {
                        float v = __fmul_rn(expf(m),
                                            __fmul_rn(refw[i], srcw[j]));
                        if (v > tspec) {
                            atomicAdd(&sHist[find_bucket(v, T, K_SPEC)], 1u);
                            unsigned p = atomicAdd(&sN, 1u);
                            if (p < SCAND) {
                                sIdx[p] = (i << 13) | j; sVal[p] = v;
                            } else {            // rare spill
                                unsigned g = atomicAdd(&dCollected, 1u);
                                if (g < CAP) {
                                    dCandIdx[g] = (i << 13) | j; dCandVal[g] = v;
                                }
                            }
                        }
                    }
                }
            }
        }
    }
    __syncthreads();
    if (tid < NTHRES && sHist[tid]) atomicAdd(&dHist[tid], sHist[tid]);
    if (tid == 0) {
        unsigned n = sN < SCAND ? sN : SCAND;
        sBase = atomicAdd(&dCollected, n);
    }
    __syncthreads();
    unsigned n = sN < SCAND ? sN : SCAND;
    for (unsigned p = tid; p < n; p += NTH) {
        unsigned g = sBase + p;
        if (g < CAP) { dCandIdx[g] = sIdx[p]; dCandVal[g] = sVal[p]; }
    }
}

// ---------------------------------------------------------------------------
__global__ void k_thres() {
    __shared__ unsigned sH[NTHRES];
    unsigned tid = threadIdx.x;
    if (tid < NTHRES) sH[tid] = dHist[tid];     // one coalesced load
    __syncthreads();
    if (tid == 0) {
        float T[NTHRES];
        build_table(T);
        unsigned cum = 0; int ks = -1;
        for (int k = 0; k <= K_SPEC; k++) {
            cum += sH[k];
            if (cum >= KCORR) { ks = k; break; }
        }
        if (ks < 0) { dDeep = 1u; dRecollect = 1u; dCollected = 0u; }
        else {
            dThres = T[ks];
            if (dCollected > CAP) { dRecollect = 1u; dCollected = 0u; }
        }
    }
}

// ---------------------------------------------------------------------------
// Fallback full-depth histogram (no-op unless dDeep).
__global__ void __launch_bounds__(NTH) k_fb_hist(const float* __restrict__ ms,
                                                 const float* __restrict__ refw,
                                                 const float* __restrict__ srcw) {
    if (dDeep == 0u) return;
    __shared__ unsigned short h[8][NTHRES][32];
    __shared__ float T[NTHRES];
    const unsigned tid = threadIdx.x;
    if (tid == 0) build_table(T);
    {
        unsigned* hz = (unsigned*)h;
        for (unsigned p = tid; p < 8u * NTHRES * 32u / 2u; p += NTH) hz[p] = 0u;
    }
    __syncthreads();
    const float tspec = T[K_SPEC];
    const unsigned wrp = tid >> 5, lane = tid & 31u;
    const unsigned step = gridDim.x * NTH;
    for (unsigned idx = blockIdx.x * NTH + tid; idx < TOTAL; idx += step) {
        unsigned i = idx >> 13, j = idx & 8191u;
        float m = __ldg(ms + i * STRIDE + j);
        float v = __fmul_rn(expf(m), __fmul_rn(refw[i], srcw[j]));
        if (!(v > tspec)) {
            int k = find_bucket(v, T, NTHRES - 1);
            h[wrp][k][lane]++;
        }
    }
    __syncthreads();
    if (tid < NTHRES) {
        unsigned s = 0;
        for (int wq = 0; wq < 8; wq++)
            for (int lq = 0; lq < 32; lq++) s += h[wq][tid][lq];
        if (s) atomicAdd(&dHist[tid], s);
    }
}

__global__ void k_thres2() {
    if (dDeep == 0u) return;
    __shared__ unsigned sH[NTHRES];
    unsigned tid = threadIdx.x;
    if (tid < NTHRES) sH[tid] = dHist[tid];
    __syncthreads();
    if (tid == 0) {
        float T[NTHRES];
        build_table(T);
        unsigned cum = 0; int ks = NTHRES - 1;
        for (int k = 0; k < NTHRES; k++) {
            cum += sH[k];
            if (cum >= KCORR) { ks = k; break; }
        }
        dThres = T[ks];
    }
}

// ---------------------------------------------------------------------------
// Re-collection with the final threshold (no-op unless dRecollect).
__global__ void __launch_bounds__(NTH) k_collect2(const float* __restrict__ ms,
                                                  const float* __restrict__ refw,
                                                  const float* __restrict__ srcw) {
    if (dRecollect == 0u) return;
    __shared__ unsigned sN, sBase;
    __shared__ unsigned sIdx[BUFCAP];
    __shared__ float    sVal[BUFCAP];
    const unsigned tid = threadIdx.x;
    if (tid == 0) sN = 0u;
    __syncthreads();
    const float th = dThres;
    float lcut = (th > 1e-30f) ? (logf(th) - 0.02f) : -1e30f;
    const unsigned step = gridDim.x * NTH;
    for (unsigned idx = blockIdx.x * NTH + tid; idx < TOTAL; idx += step) {
        unsigned i = idx >> 13, j = idx & 8191u;
        float m = __ldg(ms + i * STRIDE + j);
        if (m > lcut) {
            float v = __fmul_rn(expf(m), __fmul_rn(refw[i], srcw[j]));
            if (v > th) {
                unsigned p = atomicAdd(&sN, 1u);
                if (p < BUFCAP) { sIdx[p] = (i << 13) | j; sVal[p] = v; }
                else {
                    unsigned g = atomicAdd(&dCollected, 1u);
                    if (g < CAP) { dCandIdx[g] = (i << 13) | j; dCandVal[g] = v; }
                }
            }
        }
    }
    __syncthreads();
    if (tid == 0) {
        unsigned n = sN < BUFCAP ? sN : BUFCAP;
        sBase = atomicAdd(&dCollected, n);
    }
    __syncthreads();
    unsigned n = sN < BUFCAP ? sN : BUFCAP;
    for (unsigned p = tid; p < n; p += NTH) {
        unsigned g = sBase + p;
        if (g < CAP) { dCandIdx[g] = sIdx[p]; dCandVal[g] = sVal[p]; }
    }
}

// ---------------------------------------------------------------------------
__global__ void k_compact() {
    unsigned n = dCollected < CAP ? dCollected : CAP;
    unsigned step = gridDim.x * blockDim.x;
    float th = dThres;
    for (unsigned q = blockIdx.x * blockDim.x + threadIdx.x; q < n; q += step) {
        float v = dCandVal[q];
        if (v > th) {
            unsigned g = atomicAdd(&dNF, 1u);
            if (g < FCAP) { dFIdx[g] = dCandIdx[q]; dFVal[g] = v; }
        }
    }
}

// ---------------------------------------------------------------------------
// Rank-based ordered write: slot = #{passing candidates with smaller index}.
__global__ void k_rank(float* out) {
    __shared__ unsigned sBuf[4096];
    unsigned n = dNF < FCAP ? dNF : FCAP;
    if (blockIdx.x * blockDim.x >= n) return;   // uniform per block

    unsigned i = blockIdx.x * blockDim.x + threadIdx.x;
    unsigned Li = (i < n) ? dFIdx[i] : 0xFFFFFFFFu;
    float    Vi = (i < n) ? dFVal[i] : 0.0f;
    unsigned rank = 0;
    for (unsigned base = 0; base < n; base += 4096u) {
        unsigned m = n - base; if (m > 4096u) m = 4096u;
        __syncthreads();
        for (unsigned p = threadIdx.x; p < m; p += blockDim.x) sBuf[p] = dFIdx[base + p];
        __syncthreads();
        if (i < n)
            for (unsigned p = 0; p < m; p++) rank += (sBuf[p] < Li) ? 1u : 0u;
    }
    if (i < n && rank < (unsigned)MAXCORR) {
        unsigned r = Li >> 13, c = Li & 8191u;
        out[rank]               = (float)r;
        out[MAXCORR + rank]     = (float)c;
        out[2 * MAXCORR + rank] = Vi;
    }
}

// ---------------------------------------------------------------------------
extern "C" void kernel_launch(void* const* d_in, const int* in_sizes, int n_in,
                              void* d_out, int out_size) {
    const float* ms   = (const float*)d_in[0];   // (8193, 8193) f32
    const float* refw = (const float*)d_in[1];   // (8192,) f32
    const float* srcw = (const float*)d_in[2];   // (8192,) f32
    float* out = (float*)d_out;                  // 24576 f32

    k_reset<<<1, 128>>>();
    k_stream<<<NB_A, NTH>>>((const float4*)ms, out, out_size);
    k_process<<<2048, NTH>>>((const float4*)ms, refw, srcw);
    k_thres<<<1, 64>>>();
    k_fb_hist<<<512, NTH>>>(ms, refw, srcw);     // no-op unless dDeep
    k_thres2<<<1, 64>>>();                       // no-op unless dDeep
    k_collect2<<<512, NTH>>>(ms, refw, srcw);    // no-op unless dRecollect
    k_compact<<<64, NTH>>>();
    k_rank<<<256, NTH>>>(out);
}